// round 16
// baseline (speedup 1.0000x reference)
#include <cuda_runtime.h>
#include <cuda_bf16.h>

// Shapes: anchors (N=1024,2) f32; gt_boxes (B=128, M=256, 4) f32.
// Output f32: [matches (B*M) | ious (B,N,M)].
#define N_ANCH 1024
#define B_     128
#define M_     256

#define M_PER_CTA 32
#define NQ        8                  // m-quads per CTA: warp covers 128B/row
#define NCH       32                 // anchor chunks per CTA
#define CH        (N_ANCH / NCH)     // 32 anchors per chunk (== warp size)
#define NTHREADS  (NQ * NCH)         // 256

__device__ __forceinline__ float rcpa(float x) {
    float r; asm("rcp.approx.f32 %0, %1;" : "=f"(r) : "f"(x)); return r;
}

// Scalar correctly-rounded q = x / y, the exact ptxas div.rn fast path
// (MUFU.RCP + Newton refinement + residual fixup), written with explicit
// round-to-nearest intrinsics so the compiler cannot contract or reassociate
// (R12 lesson). Operands always normal / well-scaled (x in [2.5e-3,1],
// y in [2.5e-3,2]) so the guarded slow path of compiler div can't trip:
// bit-identical to IEEE div.rn -> rel_err stays 0. Negations fold into
// FFMA operand modifiers (free); NO inline-asm pair boundaries -> no MOV tax.
__device__ __forceinline__ float div_rn(float x, float y) {
    float r = rcpa(y);                         // MUFU.RCP
    const float e = __fmaf_rn(-y, r, 1.0f);    // 1 - y*r
    r = __fmaf_rn(r, e, r);                    // refined reciprocal
    const float q = __fmul_rn(x, r);
    const float rem = __fmaf_rn(-y, q, x);     // x - y*q
    return __fmaf_rn(rem, r, q);               // correctly-rounded quotient
}

// Proven geometry (R4/R8): grid (B, M/32) = 1024 CTAs, block 256, natural
// regs, unroll 4. Hot loop: value-only argmax (R13); pure-scalar math with
// zero asm-boundary MOVs (this round). Fold: warp-parallel shfl+ballot (R14).
__global__ void __launch_bounds__(NTHREADS)
matcher_kernel(const float* __restrict__ anchors,
               const float* __restrict__ gt,
               float* __restrict__ matches,
               float* __restrict__ ious)
{
    __shared__ float2 sWH[N_ANCH];             // {aw, ah}            8 KB
    __shared__ float  sPm[M_PER_CTA][NCH + 1]; // best iou [m][chunk] ~4 KB

    const int tid = threadIdx.x;
    const int mq  = tid & (NQ - 1);
    const int ch  = tid >> 3;
    const int b     = blockIdx.x;
    const int mbase = blockIdx.y * M_PER_CTA;
    const int m0    = mbase + 4 * mq;

    // Stage anchor widths/heights once. Centered boxes => iw = min(aw,gw)
    // bitwise (0.5w exact in fp32; clips dead since 0.05 <= sizes <= 1.0).
    for (int i = tid; i < N_ANCH; i += NTHREADS) {
        sWH[i] = reinterpret_cast<const float2*>(anchors)[i];
    }
    __syncthreads();

    float gw[4], gh[4], aB[4];
    #pragma unroll
    for (int j = 0; j < 4; j++) {
        const float4 g = reinterpret_cast<const float4*>(gt)[b * M_ + m0 + j];
        gw[j] = g.z - g.x;
        gh[j] = g.w - g.y;
        aB[j] = __fmul_rn(gw[j], gh[j]);
    }

    float best[4] = {-1.0f, -1.0f, -1.0f, -1.0f};

    // Indexed stores: compile-time offsets folded into STG [R+imm].
    float4* pp = reinterpret_cast<float4*>(
        ious + (size_t)b * N_ANCH * M_ + (size_t)ch * CH * M_ + m0);

    #pragma unroll 4
    for (int i = 0; i < CH; i++) {
        const float2 a  = sWH[ch * CH + i];
        const float  az = __fmul_rn(a.x, a.y);

        float r[4];
        #pragma unroll
        for (int j = 0; j < 4; j++) {
            const float iw    = fminf(a.x, gw[j]);
            const float ih    = fminf(a.y, gh[j]);
            const float inter = __fmul_rn(iw, ih);
            // Reference association order: (area_a + area_b) - inter.
            const float s     = __fadd_rn(az, aB[j]);
            const float uni   = __fadd_rn(s, -inter);
            r[j] = div_rn(inter, uni);
            best[j] = fmaxf(best[j], r[j]);        // value-only: 1 FMNMX
        }

        pp[(size_t)i * (M_ / 4)] = make_float4(r[0], r[1], r[2], r[3]);
    }

    #pragma unroll
    for (int j = 0; j < 4; j++)
        sPm[4 * mq + j][ch] = best[j];
    __syncthreads();

    // Warp-parallel fold + index recovery: warp w owns m-rows 4w..4w+3.
    // First-chunk-then-first-position == global first max == jnp.argmax.
    // Index recovery reads the ALREADY-STORED ious back (no recomputation
    // -> no contraction hazard); equality with bv is guaranteed since bv is
    // fmaxf over exactly those stored bits.
    const int wid  = tid >> 5;
    const int lane = tid & 31;
    #pragma unroll
    for (int k = 0; k < 4; k++) {
        const int mm = wid * 4 + k;
        const float v = sPm[mm][lane];             // lane = chunk (conflict-free)

        float bv = v;
        #pragma unroll
        for (int off = 16; off; off >>= 1)
            bv = fmaxf(bv, __shfl_xor_sync(0xffffffffu, bv, off));

        const unsigned cm = __ballot_sync(0xffffffffu, v == bv);
        const int bc = __ffs(cm) - 1;              // first chunk with the max

        const int m = mbase + mm;
        const float val = ious[(size_t)b * N_ANCH * M_
                               + (size_t)(bc * CH + lane) * M_ + m];
        const unsigned pm = __ballot_sync(0xffffffffu, val == bv);
        const int p = __ffs(pm) - 1;               // first position in chunk

        if (lane == 0)
            matches[b * M_ + m] = (float)(bc * CH + p);
    }
}

extern "C" void kernel_launch(void* const* d_in, const int* in_sizes, int n_in,
                              void* d_out, int out_size)
{
    const float* anchors = (const float*)d_in[0];
    const float* gt      = (const float*)d_in[1];
    float* out = (float*)d_out;

    const size_t ious_elems = (size_t)B_ * N_ANCH * M_;
    const size_t ious_off   = (size_t)out_size - ious_elems;

    matcher_kernel<<<dim3(B_, M_ / M_PER_CTA), NTHREADS>>>(
        anchors, gt, out, out + ious_off);
}